// round 1
// baseline (speedup 1.0000x reference)
#include <cuda_runtime.h>

// ---------------------------------------------------------------------------
// Aligner: ex = ix@W^T+b ; eo = iother@W^T+b ; S = ex@eo^T ; P = softmax(S);
//          out = P @ iother
// Shapes: B=32, L1=L2=512, D=1024 (all divide tile sizes exactly).
// ---------------------------------------------------------------------------

#define BM 128
#define BN 128
#define BK 16
#define TM 8
#define TN 8
#define PAD 4   // row stride 132 floats: keeps 16B alignment, breaks bank collisions

// Scratch (allocation-free rule: __device__ globals)
__device__ float g_ex[32L * 512 * 1024];   // 64 MB
__device__ float g_eo[32L * 512 * 1024];   // 64 MB
__device__ float g_sc[32L * 512 * 512];    // 32 MB

// Generic tiled SGEMM.
// B_IS_NK = true : Bm is [N,K] row-major (C = A @ Bm^T)   -- proj & scores
// B_IS_NK = false: Bm is [K,N] row-major (C = A @ Bm)     -- PV
template <bool B_IS_NK>
__global__ void __launch_bounds__(256, 2)
sgemm_kernel(const float* __restrict__ A, const float* __restrict__ Bm,
             const float* __restrict__ bias, float* __restrict__ C,
             int M, int N, int K, long sA, long sB, long sC)
{
    __shared__ float As[BK][BM + PAD];
    __shared__ float Bs[BK][BN + PAD];

    const long bz = blockIdx.z;
    A  += bz * sA;
    Bm += bz * sB;
    C  += bz * sC;

    const int tid  = threadIdx.x;
    const int row0 = blockIdx.y * BM;
    const int col0 = blockIdx.x * BN;

    // Loader indices
    const int ldr  = tid >> 2;          // 0..63  (row within tile, +64 second pass)
    const int ldk  = (tid & 3) << 2;    // k offset 0/4/8/12 (float4)
    const int bnr  = tid >> 5;          // 0..7   (k-row for NN B tile, +8 second pass)
    const int bnc  = (tid & 31) << 2;   // 0..124 (col offset, float4)

    // Compute indices: 16x16 thread grid of 8x8 micro-tiles
    const int ty = (tid >> 4) * TM;
    const int tx = (tid & 15) * TN;

    float acc[TM][TN];
#pragma unroll
    for (int m = 0; m < TM; m++)
#pragma unroll
        for (int n = 0; n < TN; n++) acc[m][n] = 0.0f;

    for (int k0 = 0; k0 < K; k0 += BK) {
        // --- load A tile (BM x BK), store transposed As[k][m] ---
#pragma unroll
        for (int i = 0; i < 2; i++) {
            const int r = ldr + i * 64;
            const float4 v = *reinterpret_cast<const float4*>(
                A + (long)(row0 + r) * K + k0 + ldk);
            As[ldk + 0][r] = v.x;
            As[ldk + 1][r] = v.y;
            As[ldk + 2][r] = v.z;
            As[ldk + 3][r] = v.w;
        }
        // --- load B tile ---
        if (B_IS_NK) {
            // Bm is [N,K]: tile rows col0..col0+127, store transposed Bs[k][n]
#pragma unroll
            for (int i = 0; i < 2; i++) {
                const int r = ldr + i * 64;
                const float4 v = *reinterpret_cast<const float4*>(
                    Bm + (long)(col0 + r) * K + k0 + ldk);
                Bs[ldk + 0][r] = v.x;
                Bs[ldk + 1][r] = v.y;
                Bs[ldk + 2][r] = v.z;
                Bs[ldk + 3][r] = v.w;
            }
        } else {
            // Bm is [K,N]: tile rows k0..k0+15, direct Bs[k][n]
#pragma unroll
            for (int i = 0; i < 2; i++) {
                const int kr = bnr + i * 8;
                const float4 v = *reinterpret_cast<const float4*>(
                    Bm + (long)(k0 + kr) * N + col0 + bnc);
                *reinterpret_cast<float4*>(&Bs[kr][bnc]) = v;
            }
        }
        __syncthreads();

#pragma unroll
        for (int kk = 0; kk < BK; kk++) {
            float ar[TM], br[TN];
            const float4 a0 = *reinterpret_cast<const float4*>(&As[kk][ty]);
            const float4 a1 = *reinterpret_cast<const float4*>(&As[kk][ty + 4]);
            ar[0] = a0.x; ar[1] = a0.y; ar[2] = a0.z; ar[3] = a0.w;
            ar[4] = a1.x; ar[5] = a1.y; ar[6] = a1.z; ar[7] = a1.w;
            const float4 b0 = *reinterpret_cast<const float4*>(&Bs[kk][tx]);
            const float4 b1 = *reinterpret_cast<const float4*>(&Bs[kk][tx + 4]);
            br[0] = b0.x; br[1] = b0.y; br[2] = b0.z; br[3] = b0.w;
            br[4] = b1.x; br[5] = b1.y; br[6] = b1.z; br[7] = b1.w;
#pragma unroll
            for (int m = 0; m < TM; m++)
#pragma unroll
                for (int n = 0; n < TN; n++)
                    acc[m][n] = fmaf(ar[m], br[n], acc[m][n]);
        }
        __syncthreads();
    }

    // --- epilogue (+ optional bias), vectorized stores ---
#pragma unroll
    for (int m = 0; m < TM; m++) {
        float* crow = C + (long)(row0 + ty + m) * N + col0 + tx;
#pragma unroll
        for (int n = 0; n < TN; n += 4) {
            float4 v;
            v.x = acc[m][n + 0];
            v.y = acc[m][n + 1];
            v.z = acc[m][n + 2];
            v.w = acc[m][n + 3];
            if (bias) {
                const float4 bb = *reinterpret_cast<const float4*>(bias + col0 + tx + n);
                v.x += bb.x; v.y += bb.y; v.z += bb.z; v.w += bb.w;
            }
            *reinterpret_cast<float4*>(crow + n) = v;
        }
    }
}

// Row-wise softmax over 512 elements, one block (256 threads) per row, in-place.
__global__ void __launch_bounds__(256)
softmax512_kernel(float* __restrict__ S)
{
    __shared__ float red[256];
    float* row = S + (long)blockIdx.x * 512;
    const int t = threadIdx.x;

    const float a = row[t];
    const float b = row[t + 256];

    red[t] = fmaxf(a, b);
    __syncthreads();
#pragma unroll
    for (int s = 128; s > 0; s >>= 1) {
        if (t < s) red[t] = fmaxf(red[t], red[t + s]);
        __syncthreads();
    }
    const float mx = red[0];
    __syncthreads();

    const float e0 = __expf(a - mx);
    const float e1 = __expf(b - mx);
    red[t] = e0 + e1;
    __syncthreads();
#pragma unroll
    for (int s = 128; s > 0; s >>= 1) {
        if (t < s) red[t] += red[t + s];
        __syncthreads();
    }
    const float inv = 1.0f / red[0];

    row[t]       = e0 * inv;
    row[t + 256] = e1 * inv;
}

extern "C" void kernel_launch(void* const* d_in, const int* in_sizes, int n_in,
                              void* d_out, int out_size)
{
    const float* ix = (const float*)d_in[0];   // [32, 512, 1024]
    const float* io = (const float*)d_in[1];   // [32, 512, 1024]
    const float* W  = (const float*)d_in[2];   // [1024, 1024]  (row e, col d)
    const float* b  = (const float*)d_in[3];   // [1024]
    float* out = (float*)d_out;                // [32, 512, 1024]

    float *ex, *eo, *sc;
    cudaGetSymbolAddress((void**)&ex, g_ex);
    cudaGetSymbolAddress((void**)&eo, g_eo);
    cudaGetSymbolAddress((void**)&sc, g_sc);

    const int Bn = 32, L = 512, D = 1024;
    const int Mproj = Bn * L;  // 16384

    // 1) Projections: ex = ix @ W^T + b ; eo = iother @ W^T + b   (W is [N=D, K=D])
    {
        dim3 grid(D / BN, Mproj / BM, 1);
        sgemm_kernel<true><<<grid, 256>>>(ix, W, b, ex, Mproj, D, D, 0, 0, 0);
        sgemm_kernel<true><<<grid, 256>>>(io, W, b, eo, Mproj, D, D, 0, 0, 0);
    }

    // 2) Scores: S[b] = ex[b] @ eo[b]^T  (batched NT, M=N=512, K=1024)
    {
        dim3 grid(L / BN, L / BM, Bn);
        sgemm_kernel<true><<<grid, 256>>>(ex, eo, nullptr, sc, L, L, D,
                                          (long)L * D, (long)L * D, (long)L * L);
    }

    // 3) Softmax rows (in place)
    softmax512_kernel<<<Bn * L, 256>>>(sc);

    // 4) out[b] = P[b] @ iother[b]  (batched NN, M=512, N=1024, K=512)
    {
        dim3 grid(D / BN, L / BM, Bn);
        sgemm_kernel<false><<<grid, 256>>>(sc, io, nullptr, out, L, D, L,
                                           (long)L * L, (long)L * D, (long)L * D);
    }
}

// round 2
// speedup vs baseline: 1.0578x; 1.0578x over previous
#include <cuda_runtime.h>

// ---------------------------------------------------------------------------
// Aligner: ex = ix@W^T+b ; eo = iother@W^T+b ; S = ex@eo^T ; P = softmax(S);
//          out = P @ iother
// Shapes: B=32, L1=L2=512, D=1024 (all divide tile sizes exactly).
//
// R1: fp32 GEMM with packed fma.rn.f32x2 (FFMA2, 2x fp32 pipe rate on
//     sm_103a) + 2-stage shared-memory double buffering.
// ---------------------------------------------------------------------------

#define BM 128
#define BN 128
#define BK 16
#define TM 8
#define TN 8
#define PAD 4   // row stride 132 floats: keeps 16B alignment, breaks bank collisions

// Scratch (allocation-free rule: __device__ globals)
__device__ float g_ex[32L * 512 * 1024];   // 64 MB
__device__ float g_eo[32L * 512 * 1024];   // 64 MB
__device__ float g_sc[32L * 512 * 512];    // 32 MB

// ---- packed f32x2 helpers -------------------------------------------------
__device__ __forceinline__ unsigned long long pack2(float lo, float hi) {
    unsigned long long r;
    asm("mov.b64 %0, {%1, %2};" : "=l"(r) : "f"(lo), "f"(hi));
    return r;
}
__device__ __forceinline__ void unpack2(unsigned long long v, float& lo, float& hi) {
    asm("mov.b64 {%0, %1}, %2;" : "=f"(lo), "=f"(hi) : "l"(v));
}
__device__ __forceinline__ unsigned long long ffma2(unsigned long long a,
                                                    unsigned long long b,
                                                    unsigned long long c) {
    unsigned long long d;
    asm("fma.rn.f32x2 %0, %1, %2, %3;" : "=l"(d) : "l"(a), "l"(b), "l"(c));
    return d;
}

// Generic tiled SGEMM, FFMA2 inner loop, double-buffered smem.
// B_IS_NK = true : Bm is [N,K] row-major (C = A @ Bm^T)   -- proj & scores
// B_IS_NK = false: Bm is [K,N] row-major (C = A @ Bm)     -- PV
template <bool B_IS_NK>
__global__ void __launch_bounds__(256, 2)
sgemm_kernel(const float* __restrict__ A, const float* __restrict__ Bm,
             const float* __restrict__ bias, float* __restrict__ C,
             int M, int N, int K, long sA, long sB, long sC)
{
    __shared__ float As[2][BK][BM + PAD];
    __shared__ float Bs[2][BK][BN + PAD];

    const long bz = blockIdx.z;
    A  += bz * sA;
    Bm += bz * sB;
    C  += bz * sC;

    const int tid  = threadIdx.x;
    const int row0 = blockIdx.y * BM;
    const int col0 = blockIdx.x * BN;

    // Loader indices
    const int ldr  = tid >> 2;          // 0..63  (row within tile, +64 second pass)
    const int ldk  = (tid & 3) << 2;    // k offset 0/4/8/12 (float4)
    const int bnr  = tid >> 5;          // 0..7   (k-row for NN B tile, +8 second pass)
    const int bnc  = (tid & 31) << 2;   // 0..124 (col offset, float4)

    // Compute indices: 16x16 thread grid of 8x8 micro-tiles
    const int ty = (tid >> 4) * TM;
    const int tx = (tid & 15) * TN;

    // Accumulators: f32x2 pairs along m.
    // acc2[mp][n] = ( C[ty+2mp][tx+n], C[ty+2mp+1][tx+n] )
    unsigned long long acc2[TM / 2][TN];
#pragma unroll
    for (int mp = 0; mp < TM / 2; mp++)
#pragma unroll
        for (int n = 0; n < TN; n++) acc2[mp][n] = 0ULL;

    float4 ra[2], rb[2];

    // ---- prologue: fetch + stage tile 0 ----
#pragma unroll
    for (int i = 0; i < 2; i++)
        ra[i] = *reinterpret_cast<const float4*>(
            A + (long)(row0 + ldr + i * 64) * K + 0 + ldk);
    if (B_IS_NK) {
#pragma unroll
        for (int i = 0; i < 2; i++)
            rb[i] = *reinterpret_cast<const float4*>(
                Bm + (long)(col0 + ldr + i * 64) * K + 0 + ldk);
    } else {
#pragma unroll
        for (int i = 0; i < 2; i++)
            rb[i] = *reinterpret_cast<const float4*>(
                Bm + (long)(0 + bnr + i * 8) * N + col0 + bnc);
    }
#pragma unroll
    for (int i = 0; i < 2; i++) {
        const int r = ldr + i * 64;
        As[0][ldk + 0][r] = ra[i].x;
        As[0][ldk + 1][r] = ra[i].y;
        As[0][ldk + 2][r] = ra[i].z;
        As[0][ldk + 3][r] = ra[i].w;
    }
    if (B_IS_NK) {
#pragma unroll
        for (int i = 0; i < 2; i++) {
            const int r = ldr + i * 64;
            Bs[0][ldk + 0][r] = rb[i].x;
            Bs[0][ldk + 1][r] = rb[i].y;
            Bs[0][ldk + 2][r] = rb[i].z;
            Bs[0][ldk + 3][r] = rb[i].w;
        }
    } else {
#pragma unroll
        for (int i = 0; i < 2; i++)
            *reinterpret_cast<float4*>(&Bs[0][bnr + i * 8][bnc]) = rb[i];
    }
    __syncthreads();

    int cur = 0;
    for (int k0 = 0; k0 < K; k0 += BK) {
        const int kn = k0 + BK;
        const bool has_next = kn < K;

        // ---- issue global fetches for next tile (latency hidden by compute) ----
        if (has_next) {
#pragma unroll
            for (int i = 0; i < 2; i++)
                ra[i] = *reinterpret_cast<const float4*>(
                    A + (long)(row0 + ldr + i * 64) * K + kn + ldk);
            if (B_IS_NK) {
#pragma unroll
                for (int i = 0; i < 2; i++)
                    rb[i] = *reinterpret_cast<const float4*>(
                        Bm + (long)(col0 + ldr + i * 64) * K + kn + ldk);
            } else {
#pragma unroll
                for (int i = 0; i < 2; i++)
                    rb[i] = *reinterpret_cast<const float4*>(
                        Bm + (long)(kn + bnr + i * 8) * N + col0 + bnc);
            }
        }

        // ---- compute on current buffers ----
#pragma unroll
        for (int kk = 0; kk < BK; kk++) {
            // a pairs come packed for free from 16B shared loads
            const ulonglong2 a01 =
                *reinterpret_cast<const ulonglong2*>(&As[cur][kk][ty]);
            const ulonglong2 a23 =
                *reinterpret_cast<const ulonglong2*>(&As[cur][kk][ty + 4]);
            unsigned long long av[4];
            av[0] = a01.x; av[1] = a01.y; av[2] = a23.x; av[3] = a23.y;

            const float4 b0 = *reinterpret_cast<const float4*>(&Bs[cur][kk][tx]);
            const float4 b1 = *reinterpret_cast<const float4*>(&Bs[cur][kk][tx + 4]);
            float bf[8];
            bf[0] = b0.x; bf[1] = b0.y; bf[2] = b0.z; bf[3] = b0.w;
            bf[4] = b1.x; bf[5] = b1.y; bf[6] = b1.z; bf[7] = b1.w;

#pragma unroll
            for (int n = 0; n < TN; n++) {
                const unsigned long long bs = pack2(bf[n], bf[n]);
#pragma unroll
                for (int mp = 0; mp < TM / 2; mp++)
                    acc2[mp][n] = ffma2(av[mp], bs, acc2[mp][n]);
            }
        }

        // ---- stage next tile into the other buffer ----
        if (has_next) {
            const int w = cur ^ 1;
#pragma unroll
            for (int i = 0; i < 2; i++) {
                const int r = ldr + i * 64;
                As[w][ldk + 0][r] = ra[i].x;
                As[w][ldk + 1][r] = ra[i].y;
                As[w][ldk + 2][r] = ra[i].z;
                As[w][ldk + 3][r] = ra[i].w;
            }
            if (B_IS_NK) {
#pragma unroll
                for (int i = 0; i < 2; i++) {
                    const int r = ldr + i * 64;
                    Bs[w][ldk + 0][r] = rb[i].x;
                    Bs[w][ldk + 1][r] = rb[i].y;
                    Bs[w][ldk + 2][r] = rb[i].z;
                    Bs[w][ldk + 3][r] = rb[i].w;
                }
            } else {
#pragma unroll
                for (int i = 0; i < 2; i++)
                    *reinterpret_cast<float4*>(&Bs[w][bnr + i * 8][bnc]) = rb[i];
            }
            __syncthreads();
            cur = w;
        }
    }

    // ---- epilogue (+ optional bias), vectorized stores ----
#pragma unroll
    for (int mp = 0; mp < TM / 2; mp++) {
        float r0[TN], r1[TN];
#pragma unroll
        for (int n = 0; n < TN; n++) unpack2(acc2[mp][n], r0[n], r1[n]);

        float4 bb0, bb1;
        if (bias) {
            bb0 = *reinterpret_cast<const float4*>(bias + col0 + tx);
            bb1 = *reinterpret_cast<const float4*>(bias + col0 + tx + 4);
        } else {
            bb0 = make_float4(0.f, 0.f, 0.f, 0.f);
            bb1 = bb0;
        }

        float* crow0 = C + (long)(row0 + ty + 2 * mp) * N + col0 + tx;
        float* crow1 = C + (long)(row0 + ty + 2 * mp + 1) * N + col0 + tx;

        float4 v;
        v.x = r0[0] + bb0.x; v.y = r0[1] + bb0.y; v.z = r0[2] + bb0.z; v.w = r0[3] + bb0.w;
        *reinterpret_cast<float4*>(crow0) = v;
        v.x = r0[4] + bb1.x; v.y = r0[5] + bb1.y; v.z = r0[6] + bb1.z; v.w = r0[7] + bb1.w;
        *reinterpret_cast<float4*>(crow0 + 4) = v;
        v.x = r1[0] + bb0.x; v.y = r1[1] + bb0.y; v.z = r1[2] + bb0.z; v.w = r1[3] + bb0.w;
        *reinterpret_cast<float4*>(crow1) = v;
        v.x = r1[4] + bb1.x; v.y = r1[5] + bb1.y; v.z = r1[6] + bb1.z; v.w = r1[7] + bb1.w;
        *reinterpret_cast<float4*>(crow1 + 4) = v;
    }
}

// Row-wise softmax over 512 elements, one block (256 threads) per row, in-place.
__global__ void __launch_bounds__(256)
softmax512_kernel(float* __restrict__ S)
{
    __shared__ float red[256];
    float* row = S + (long)blockIdx.x * 512;
    const int t = threadIdx.x;

    const float a = row[t];
    const float b = row[t + 256];

    red[t] = fmaxf(a, b);
    __syncthreads();
#pragma unroll
    for (int s = 128; s > 0; s >>= 1) {
        if (t < s) red[t] = fmaxf(red[t], red[t + s]);
        __syncthreads();
    }
    const float mx = red[0];
    __syncthreads();

    const float e0 = __expf(a - mx);
    const float e1 = __expf(b - mx);
    red[t] = e0 + e1;
    __syncthreads();
#pragma unroll
    for (int s = 128; s > 0; s >>= 1) {
        if (t < s) red[t] += red[t + s];
        __syncthreads();
    }
    const float inv = 1.0f / red[0];

    row[t]       = e0 * inv;
    row[t + 256] = e1 * inv;
}

extern "C" void kernel_launch(void* const* d_in, const int* in_sizes, int n_in,
                              void* d_out, int out_size)
{
    const float* ix = (const float*)d_in[0];   // [32, 512, 1024]
    const float* io = (const float*)d_in[1];   // [32, 512, 1024]
    const float* W  = (const float*)d_in[2];   // [1024, 1024]  (row e, col d)
    const float* b  = (const float*)d_in[3];   // [1024]
    float* out = (float*)d_out;                // [32, 512, 1024]

    float *ex, *eo, *sc;
    cudaGetSymbolAddress((void**)&ex, g_ex);
    cudaGetSymbolAddress((void**)&eo, g_eo);
    cudaGetSymbolAddress((void**)&sc, g_sc);

    const int Bn = 32, L = 512, D = 1024;
    const int Mproj = Bn * L;  // 16384

    // 1) Projections: ex = ix @ W^T + b ; eo = iother @ W^T + b   (W is [N=D, K=D])
    {
        dim3 grid(D / BN, Mproj / BM, 1);
        sgemm_kernel<true><<<grid, 256>>>(ix, W, b, ex, Mproj, D, D, 0, 0, 0);
        sgemm_kernel<true><<<grid, 256>>>(io, W, b, eo, Mproj, D, D, 0, 0, 0);
    }

    // 2) Scores: S[b] = ex[b] @ eo[b]^T  (batched NT, M=N=512, K=1024)
    {
        dim3 grid(L / BN, L / BM, Bn);
        sgemm_kernel<true><<<grid, 256>>>(ex, eo, nullptr, sc, L, L, D,
                                          (long)L * D, (long)L * D, (long)L * L);
    }

    // 3) Softmax rows (in place)
    softmax512_kernel<<<Bn * L, 256>>>(sc);

    // 4) out[b] = P[b] @ iother[b]  (batched NN, M=512, N=1024, K=512)
    {
        dim3 grid(D / BN, L / BM, Bn);
        sgemm_kernel<false><<<grid, 256>>>(sc, io, nullptr, out, L, D, L,
                                           (long)L * L, (long)L * D, (long)L * D);
    }
}

// round 4
// speedup vs baseline: 1.9406x; 1.8345x over previous
#include <cuda_runtime.h>
#include <cuda_bf16.h>
#include <cstdint>

// ---------------------------------------------------------------------------
// Aligner via mma.sync bf16 (HMMA tensor pipe) with 2-term hi/lo split.
//   ex = ix@W^T+b ; eo = io@W^T+b ; S = ex@eo^T ; P = softmax(S); out = P@io
// fp32 GEMM == 3 bf16 phases accumulated in fp32 registers:
//   A_hi*B_hi + A_hi*B_lo + A_lo*B_hi
// Shapes: B=32, L=512, D=1024.
// ---------------------------------------------------------------------------

typedef unsigned short u16;  // raw bf16 bits

// ======================= scratch (device globals) ===========================
__device__ u16   g_ixs [16384L * 2048];     // ix split  [M, hi(0..1023)|lo]
__device__ u16   g_ios [16384L * 2048];     // io split
__device__ u16   g_iosT[32L * 1024 * 1024]; // io^T split per batch [d, m_hi|m_lo]
__device__ u16   g_ws  [1024L * 2048];      // W split
__device__ u16   g_exs [16384L * 2048];     // ex split (proj output)
__device__ u16   g_eos [16384L * 2048];     // eo split
__device__ float g_sc  [32L * 512 * 512];   // scores fp32
__device__ u16   g_ps  [32L * 512 * 1024];  // softmax probs split [l, m_hi|m_lo]

// ======================= PTX helpers ========================================
__device__ __forceinline__ uint32_t smem_u32(const void* p) {
    uint32_t a;
    asm("{ .reg .u64 t; cvta.to.shared.u64 t, %1; cvt.u32.u64 %0, t; }"
        : "=r"(a) : "l"(p));
    return a;
}

__device__ __forceinline__ void cp_async16(uint32_t saddr, const void* gaddr) {
    asm volatile("cp.async.cg.shared.global [%0], [%1], 16;"
                 :: "r"(saddr), "l"(gaddr) : "memory");
}
__device__ __forceinline__ void cp_commit() {
    asm volatile("cp.async.commit_group;" ::: "memory");
}
template <int N>
__device__ __forceinline__ void cp_wait() {
    asm volatile("cp.async.wait_group %0;" :: "n"(N) : "memory");
}

__device__ __forceinline__ void ldsm_x4(uint32_t* r, uint32_t addr) {
    asm volatile("ldmatrix.sync.aligned.m8n8.x4.shared.b16 {%0,%1,%2,%3}, [%4];"
                 : "=r"(r[0]), "=r"(r[1]), "=r"(r[2]), "=r"(r[3]) : "r"(addr));
}

__device__ __forceinline__ void mma_bf16(float* c, const uint32_t* a,
                                         const uint32_t* b) {
    asm volatile(
        "mma.sync.aligned.m16n8k16.row.col.f32.bf16.bf16.f32 "
        "{%0,%1,%2,%3}, {%4,%5,%6,%7}, {%8,%9}, {%0,%1,%2,%3};"
        : "+f"(c[0]), "+f"(c[1]), "+f"(c[2]), "+f"(c[3])
        : "r"(a[0]), "r"(a[1]), "r"(a[2]), "r"(a[3]), "r"(b[0]), "r"(b[1]));
}

// ======================= split helpers ======================================
__device__ __forceinline__ void split2(float v, __nv_bfloat16& h, __nv_bfloat16& l) {
    h = __float2bfloat16(v);
    l = __float2bfloat16(v - __bfloat162float(h));
}

// fp32 [R, C] -> bf16 [R, 2C] (hi | lo). One float4 per thread.
__global__ void __launch_bounds__(256)
split_kernel(const float* __restrict__ in, u16* __restrict__ out, int C)
{
    const long idx = (long)blockIdx.x * 256 + threadIdx.x;
    const long e = idx * 4;
    const long r = e / C;
    const int  c = (int)(e - r * C);
    const float4 v = *reinterpret_cast<const float4*>(in + e);
    __nv_bfloat16 h0, h1, h2, h3, l0, l1, l2, l3;
    split2(v.x, h0, l0); split2(v.y, h1, l1); split2(v.z, h2, l2); split2(v.w, h3, l3);
    __nv_bfloat16* oh = reinterpret_cast<__nv_bfloat16*>(out + r * (2L * C) + c);
    __nv_bfloat16* ol = reinterpret_cast<__nv_bfloat16*>(out + r * (2L * C) + C + c);
    *reinterpret_cast<__nv_bfloat162*>(oh)     = __halves2bfloat162(h0, h1);
    *reinterpret_cast<__nv_bfloat162*>(oh + 2) = __halves2bfloat162(h2, h3);
    *reinterpret_cast<__nv_bfloat162*>(ol)     = __halves2bfloat162(l0, l1);
    *reinterpret_cast<__nv_bfloat162*>(ol + 2) = __halves2bfloat162(l2, l3);
}

// io [32,512,1024] fp32 -> ioT split [32,1024, 512hi|512lo] bf16
__global__ void __launch_bounds__(256)
transpose_split_kernel(const float* __restrict__ in, u16* __restrict__ out)
{
    __shared__ float t[32][33];
    const int b  = blockIdx.z;
    const int d0 = blockIdx.x * 32;
    const int m0 = blockIdx.y * 32;
    const int tx = threadIdx.x & 31;
    const int ty = threadIdx.x >> 5;   // 0..7
    const float* ib = in + (long)b * 512 * 1024;
#pragma unroll
    for (int i = 0; i < 4; i++)
        t[ty + 8 * i][tx] = ib[(long)(m0 + ty + 8 * i) * 1024 + d0 + tx];
    __syncthreads();
    u16* ob = out + (long)b * 1024 * 1024;
#pragma unroll
    for (int i = 0; i < 4; i++) {
        const int d = d0 + ty + 8 * i;
        const int m = m0 + tx;
        __nv_bfloat16 h, l;
        split2(t[tx][ty + 8 * i], h, l);
        *reinterpret_cast<__nv_bfloat16*>(&ob[(long)d * 1024 + m])       = h;
        *reinterpret_cast<__nv_bfloat16*>(&ob[(long)d * 1024 + 512 + m]) = l;
    }
}

// ======================= mma.sync GEMM ======================================
// C[M,N] = A[M, 2K] (*) B[N, 2K]  via 3 bf16 phases, fp32 reg accumulate.
// CTA tile 128x128, BK=32, 8 warps (warp grid 4 M x 2 N, warp tile 32x64).
// MODE 0: fp32 out to Cf;  MODE 1: bias add + re-split to Cs (hi|lo at loOff).
#define LDS_STRIDE 40   // elements per smem row (32 + 8 pad) -> conflict-free

template <int MODE>
__global__ void __launch_bounds__(256)
gemm_mma(const u16* __restrict__ A, const u16* __restrict__ B,
         const float* __restrict__ bias, float* __restrict__ Cf,
         u16* __restrict__ Cs,
         int K, long sA, long sB, long sC, int ldc, int loOff)
{
    __shared__ u16 sA_t[2][128 * LDS_STRIDE];
    __shared__ u16 sB_t[2][128 * LDS_STRIDE];

    const int tid  = threadIdx.x;
    const int wid  = tid >> 5;
    const int lane = tid & 31;

    const long bz = blockIdx.z;
    A += bz * sA;
    B += bz * sB;
    const int row0 = blockIdx.y * 128;
    const int col0 = blockIdx.x * 128;
    const long lda = 2L * K;

    const int nkc = K / 32;
    const int nc  = 3 * nkc;

    const uint32_t sAu[2] = { smem_u32(sA_t[0]), smem_u32(sA_t[1]) };
    const uint32_t sBu[2] = { smem_u32(sB_t[0]), smem_u32(sB_t[1]) };

    // copy mapping: vector v = tid + 256*j (j=0,1); row = v>>2, 16B col = v&3
    const int cr0 = tid >> 2;
    const int cc  = tid & 3;

    // warp tiling: warp_m in 0..3 (32 rows each), warp_n in 0..1 (64 cols each)
    const int warp_m = wid & 3;
    const int warp_n = wid >> 2;

    float acc[2][8][4];
#pragma unroll
    for (int mt = 0; mt < 2; mt++)
#pragma unroll
        for (int nt = 0; nt < 8; nt++)
#pragma unroll
            for (int i = 0; i < 4; i++) acc[mt][nt][i] = 0.0f;

    // per-lane ldmatrix source offsets (element units)
    const int a_row = warp_m * 32 + (lane & 15);
    const int a_colb = (lane >> 4) << 3;
    const int b_row = warp_n * 64 + (lane & 7) + ((lane >> 4) << 3);
    const int b_colb = ((lane >> 3) & 1) << 3;

    auto stage_copy = [&](int buf, int ci) {
        const int ph = ci / nkc;
        const int kc = ci - ph * nkc;
        const int aoff = ((ph == 2) ? K : 0) + kc * 32;
        const int boff = ((ph == 1) ? K : 0) + kc * 32;
#pragma unroll
        for (int j = 0; j < 2; j++) {
            const int r = cr0 + 64 * j;
            const uint32_t so = (uint32_t)r * (LDS_STRIDE * 2) + (uint32_t)cc * 16u;
            cp_async16(sAu[buf] + so, A + (long)(row0 + r) * lda + aoff + cc * 8);
            cp_async16(sBu[buf] + so, B + (long)(col0 + r) * lda + boff + cc * 8);
        }
        cp_commit();
    };

    stage_copy(0, 0);

    for (int ci = 0; ci < nc; ci++) {
        const int buf = ci & 1;
        if (ci + 1 < nc) {
            stage_copy(buf ^ 1, ci + 1);
            cp_wait<1>();
        } else {
            cp_wait<0>();
        }
        __syncthreads();

        const uint32_t au = sAu[buf];
        const uint32_t bu = sBu[buf];
#pragma unroll
        for (int kk = 0; kk < 2; kk++) {
            uint32_t afr[2][4];
#pragma unroll
            for (int mt = 0; mt < 2; mt++) {
                const uint32_t addr = au +
                    (uint32_t)(a_row + mt * 16) * (LDS_STRIDE * 2) +
                    (uint32_t)(kk * 16 + a_colb) * 2;
                ldsm_x4(afr[mt], addr);
            }
            uint32_t bfr[8][2];
#pragma unroll
            for (int nt2 = 0; nt2 < 4; nt2++) {
                uint32_t r4[4];
                const uint32_t addr = bu +
                    (uint32_t)(b_row + nt2 * 16) * (LDS_STRIDE * 2) +
                    (uint32_t)(kk * 16 + b_colb) * 2;
                ldsm_x4(r4, addr);
                bfr[2 * nt2][0] = r4[0]; bfr[2 * nt2][1] = r4[1];
                bfr[2 * nt2 + 1][0] = r4[2]; bfr[2 * nt2 + 1][1] = r4[3];
            }
#pragma unroll
            for (int mt = 0; mt < 2; mt++)
#pragma unroll
                for (int nt = 0; nt < 8; nt++)
                    mma_bf16(acc[mt][nt], afr[mt], bfr[nt]);
        }
        __syncthreads();
    }

    // ---- epilogue ----
    const int er0 = row0 + warp_m * 32 + (lane >> 2);
    const int ec0 = col0 + warp_n * 64 + (lane & 3) * 2;
#pragma unroll
    for (int mt = 0; mt < 2; mt++) {
#pragma unroll
        for (int nt = 0; nt < 8; nt++) {
            const int r0 = er0 + mt * 16;
            const int r1 = r0 + 8;
            const int c  = ec0 + nt * 8;
            if (MODE == 0) {
                float* p0 = Cf + bz * sC + (long)r0 * ldc + c;
                float* p1 = Cf + bz * sC + (long)r1 * ldc + c;
                p0[0] = acc[mt][nt][0]; p0[1] = acc[mt][nt][1];
                p1[0] = acc[mt][nt][2]; p1[1] = acc[mt][nt][3];
            } else {
                const float b0 = bias[c], b1 = bias[c + 1];
                __nv_bfloat16 h0, h1, l0, l1;
                u16* q0 = Cs + (long)r0 * ldc + c;
                split2(acc[mt][nt][0] + b0, h0, l0);
                split2(acc[mt][nt][1] + b1, h1, l1);
                *reinterpret_cast<__nv_bfloat162*>(q0) = __halves2bfloat162(h0, h1);
                *reinterpret_cast<__nv_bfloat162*>(q0 + loOff) = __halves2bfloat162(l0, l1);
                u16* q1 = Cs + (long)r1 * ldc + c;
                split2(acc[mt][nt][2] + b0, h0, l0);
                split2(acc[mt][nt][3] + b1, h1, l1);
                *reinterpret_cast<__nv_bfloat162*>(q1) = __halves2bfloat162(h0, h1);
                *reinterpret_cast<__nv_bfloat162*>(q1 + loOff) = __halves2bfloat162(l0, l1);
            }
        }
    }
}

// ======================= softmax + split ====================================
__global__ void __launch_bounds__(256)
softmax512_split_kernel(const float* __restrict__ S, u16* __restrict__ P)
{
    __shared__ float red[256];
    const float* row = S + (long)blockIdx.x * 512;
    u16* prow = P + (long)blockIdx.x * 1024;
    const int t = threadIdx.x;

    const float a = row[t];
    const float b = row[t + 256];

    red[t] = fmaxf(a, b);
    __syncthreads();
#pragma unroll
    for (int s = 128; s > 0; s >>= 1) {
        if (t < s) red[t] = fmaxf(red[t], red[t + s]);
        __syncthreads();
    }
    const float mx = red[0];
    __syncthreads();

    const float e0 = __expf(a - mx);
    const float e1 = __expf(b - mx);
    red[t] = e0 + e1;
    __syncthreads();
#pragma unroll
    for (int s = 128; s > 0; s >>= 1) {
        if (t < s) red[t] += red[t + s];
        __syncthreads();
    }
    const float inv = 1.0f / red[0];

    __nv_bfloat16 h, l;
    split2(e0 * inv, h, l);
    *reinterpret_cast<__nv_bfloat16*>(&prow[t])             = h;
    *reinterpret_cast<__nv_bfloat16*>(&prow[512 + t])       = l;
    split2(e1 * inv, h, l);
    *reinterpret_cast<__nv_bfloat16*>(&prow[t + 256])       = h;
    *reinterpret_cast<__nv_bfloat16*>(&prow[512 + t + 256]) = l;
}

// ======================= launch =============================================
extern "C" void kernel_launch(void* const* d_in, const int* in_sizes, int n_in,
                              void* d_out, int out_size)
{
    const float* ix = (const float*)d_in[0];   // [32, 512, 1024]
    const float* io = (const float*)d_in[1];   // [32, 512, 1024]
    const float* W  = (const float*)d_in[2];   // [1024, 1024]
    const float* bi = (const float*)d_in[3];   // [1024]
    float* out = (float*)d_out;                // [32, 512, 1024]

    u16 *ixs, *ios, *iosT, *ws, *exs, *eos, *ps;
    float* sc;
    cudaGetSymbolAddress((void**)&ixs,  g_ixs);
    cudaGetSymbolAddress((void**)&ios,  g_ios);
    cudaGetSymbolAddress((void**)&iosT, g_iosT);
    cudaGetSymbolAddress((void**)&ws,   g_ws);
    cudaGetSymbolAddress((void**)&exs,  g_exs);
    cudaGetSymbolAddress((void**)&eos,  g_eos);
    cudaGetSymbolAddress((void**)&sc,   g_sc);
    cudaGetSymbolAddress((void**)&ps,   g_ps);

    const int Bn = 32, L = 512, D = 1024;
    const int Mproj = Bn * L;  // 16384

    // 0) splits
    split_kernel<<<(Mproj * (long)D) / 1024, 256>>>(ix, ixs, D);
    split_kernel<<<(Mproj * (long)D) / 1024, 256>>>(io, ios, D);
    split_kernel<<<(D * (long)D) / 1024, 256>>>(W, ws, D);
    {
        dim3 g(D / 32, L / 32, Bn);
        transpose_split_kernel<<<g, 256>>>(io, iosT);
    }

    // 1) projections -> split outputs (bias fused)
    {
        dim3 g(D / 128, Mproj / 128, 1);
        gemm_mma<1><<<g, 256>>>(ixs, ws, bi, nullptr, exs, D, 0, 0, 0, 2 * D, D);
        gemm_mma<1><<<g, 256>>>(ios, ws, bi, nullptr, eos, D, 0, 0, 0, 2 * D, D);
    }

    // 2) scores: S[b] = ex[b] @ eo[b]^T   (fp32 out)
    {
        dim3 g(L / 128, L / 128, Bn);
        gemm_mma<0><<<g, 256>>>(exs, eos, nullptr, sc, nullptr,
                                D, (long)L * 2 * D, (long)L * 2 * D,
                                (long)L * L, L, 0);
    }

    // 3) softmax + split probs
    softmax512_split_kernel<<<Bn * L, 256>>>(sc, ps);

    // 4) out[b] = P[b] @ ioT[b]^T  (NT with pre-transposed io)
    {
        dim3 g(D / 128, L / 128, Bn);
        gemm_mma<0><<<g, 256>>>(ps, iosT, nullptr, out, nullptr,
                                L, (long)L * 2 * L, (long)D * 2 * L,
                                (long)L * D, D, 0);
    }
}

// round 5
// speedup vs baseline: 2.1555x; 1.1107x over previous
#include <cuda_runtime.h>
#include <cuda_bf16.h>
#include <cstdint>

// ---------------------------------------------------------------------------
// Aligner via mma.sync bf16 (HMMA tensor pipe) with 2-term hi/lo split.
//   ex = ix@W^T+b ; eo = io@W^T+b ; S = ex@eo^T ; P = softmax(S); out = P@io
// fp32 GEMM == 3 bf16 phases accumulated in fp32 registers:
//   A_hi*B_hi + A_hi*B_lo + A_lo*B_hi
// R4: 3-stage cp.async pipeline, 1 barrier/chunk, 2 CTAs/SM.
// ---------------------------------------------------------------------------

typedef unsigned short u16;  // raw bf16 bits

// ======================= scratch (device globals) ===========================
__device__ u16   g_ixs [16384L * 2048];     // ix split  [M, hi(0..1023)|lo]
__device__ u16   g_ios [16384L * 2048];     // io split
__device__ u16   g_iosT[32L * 1024 * 1024]; // io^T split per batch [d, m_hi|m_lo]
__device__ u16   g_ws  [1024L * 2048];      // W split
__device__ u16   g_exs [16384L * 2048];     // ex split (proj output)
__device__ u16   g_eos [16384L * 2048];     // eo split
__device__ float g_sc  [32L * 512 * 512];   // scores fp32
__device__ u16   g_ps  [32L * 512 * 1024];  // softmax probs split [l, m_hi|m_lo]

// ======================= PTX helpers ========================================
__device__ __forceinline__ uint32_t smem_u32(const void* p) {
    uint32_t a;
    asm("{ .reg .u64 t; cvta.to.shared.u64 t, %1; cvt.u32.u64 %0, t; }"
        : "=r"(a) : "l"(p));
    return a;
}

__device__ __forceinline__ void cp_async16(uint32_t saddr, const void* gaddr) {
    asm volatile("cp.async.cg.shared.global [%0], [%1], 16;"
                 :: "r"(saddr), "l"(gaddr) : "memory");
}
__device__ __forceinline__ void cp_commit() {
    asm volatile("cp.async.commit_group;" ::: "memory");
}
template <int N>
__device__ __forceinline__ void cp_wait() {
    asm volatile("cp.async.wait_group %0;" :: "n"(N) : "memory");
}

__device__ __forceinline__ void ldsm_x4(uint32_t* r, uint32_t addr) {
    asm volatile("ldmatrix.sync.aligned.m8n8.x4.shared.b16 {%0,%1,%2,%3}, [%4];"
                 : "=r"(r[0]), "=r"(r[1]), "=r"(r[2]), "=r"(r[3]) : "r"(addr));
}

__device__ __forceinline__ void mma_bf16(float* c, const uint32_t* a,
                                         const uint32_t* b) {
    asm volatile(
        "mma.sync.aligned.m16n8k16.row.col.f32.bf16.bf16.f32 "
        "{%0,%1,%2,%3}, {%4,%5,%6,%7}, {%8,%9}, {%0,%1,%2,%3};"
        : "+f"(c[0]), "+f"(c[1]), "+f"(c[2]), "+f"(c[3])
        : "r"(a[0]), "r"(a[1]), "r"(a[2]), "r"(a[3]), "r"(b[0]), "r"(b[1]));
}

// ======================= split helpers ======================================
__device__ __forceinline__ void split2(float v, __nv_bfloat16& h, __nv_bfloat16& l) {
    h = __float2bfloat16(v);
    l = __float2bfloat16(v - __bfloat162float(h));
}

// fp32 [R, C] -> bf16 [R, 2C] (hi | lo). One float4 per thread.
__global__ void __launch_bounds__(256)
split_kernel(const float* __restrict__ in, u16* __restrict__ out, int C)
{
    const long idx = (long)blockIdx.x * 256 + threadIdx.x;
    const long e = idx * 4;
    const long r = e / C;
    const int  c = (int)(e - r * C);
    const float4 v = *reinterpret_cast<const float4*>(in + e);
    __nv_bfloat16 h0, h1, h2, h3, l0, l1, l2, l3;
    split2(v.x, h0, l0); split2(v.y, h1, l1); split2(v.z, h2, l2); split2(v.w, h3, l3);
    __nv_bfloat16* oh = reinterpret_cast<__nv_bfloat16*>(out + r * (2L * C) + c);
    __nv_bfloat16* ol = reinterpret_cast<__nv_bfloat16*>(out + r * (2L * C) + C + c);
    *reinterpret_cast<__nv_bfloat162*>(oh)     = __halves2bfloat162(h0, h1);
    *reinterpret_cast<__nv_bfloat162*>(oh + 2) = __halves2bfloat162(h2, h3);
    *reinterpret_cast<__nv_bfloat162*>(ol)     = __halves2bfloat162(l0, l1);
    *reinterpret_cast<__nv_bfloat162*>(ol + 2) = __halves2bfloat162(l2, l3);
}

// io [32,512,1024] fp32 -> ioT split [32,1024, 512hi|512lo] bf16
__global__ void __launch_bounds__(256)
transpose_split_kernel(const float* __restrict__ in, u16* __restrict__ out)
{
    __shared__ float t[32][33];
    const int b  = blockIdx.z;
    const int d0 = blockIdx.x * 32;
    const int m0 = blockIdx.y * 32;
    const int tx = threadIdx.x & 31;
    const int ty = threadIdx.x >> 5;   // 0..7
    const float* ib = in + (long)b * 512 * 1024;
#pragma unroll
    for (int i = 0; i < 4; i++)
        t[ty + 8 * i][tx] = ib[(long)(m0 + ty + 8 * i) * 1024 + d0 + tx];
    __syncthreads();
    u16* ob = out + (long)b * 1024 * 1024;
#pragma unroll
    for (int i = 0; i < 4; i++) {
        const int d = d0 + ty + 8 * i;
        const int m = m0 + tx;
        __nv_bfloat16 h, l;
        split2(t[tx][ty + 8 * i], h, l);
        *reinterpret_cast<__nv_bfloat16*>(&ob[(long)d * 1024 + m])       = h;
        *reinterpret_cast<__nv_bfloat16*>(&ob[(long)d * 1024 + 512 + m]) = l;
    }
}

// ======================= mma.sync GEMM ======================================
// C[M,N] = A[M, 2K] (*) B[N, 2K]  via 3 bf16 phases, fp32 reg accumulate.
// CTA tile 128x128, BK=32, 8 warps (4Mx2N grid, warp tile 32x64).
// 3-stage cp.async pipeline, 1 __syncthreads per chunk, 2 CTAs/SM.
// MODE 0: fp32 out to Cf;  MODE 1: bias add + re-split to Cs (hi|lo at loOff).
#define LDS_STRIDE 40                        // 32 + 8 pad elements per row
#define TILE_BYTES (128 * LDS_STRIDE * 2)    // 10240 B per tile per stage
#define GEMM_SMEM (6 * TILE_BYTES)           // 3 stages x (A + B) = 61440 B

template <int MODE>
__global__ void __launch_bounds__(256, 2)
gemm_mma(const u16* __restrict__ A, const u16* __restrict__ B,
         const float* __restrict__ bias, float* __restrict__ Cf,
         u16* __restrict__ Cs,
         int K, long sA, long sB, long sC, int ldc, int loOff)
{
    extern __shared__ char dynsmem[];

    const int tid  = threadIdx.x;
    const int wid  = tid >> 5;
    const int lane = tid & 31;

    const long bz = blockIdx.z;
    A += bz * sA;
    B += bz * sB;
    const int row0 = blockIdx.y * 128;
    const int col0 = blockIdx.x * 128;
    const long lda = 2L * K;

    const int nkc = K / 32;
    const int nc  = 3 * nkc;

    const uint32_t sbase = smem_u32(dynsmem);
    // stage s: A tile at sbase + s*TILE_BYTES, B tile at sbase + (3+s)*TILE_BYTES

    // copy mapping: vector v = tid + 256*j (j=0,1); row = v>>2, 16B col = v&3
    const int cr0 = tid >> 2;
    const int cc  = tid & 3;

    // warp tiling: warp_m in 0..3 (32 rows each), warp_n in 0..1 (64 cols each)
    const int warp_m = wid & 3;
    const int warp_n = wid >> 2;

    float acc[2][8][4];
#pragma unroll
    for (int mt = 0; mt < 2; mt++)
#pragma unroll
        for (int nt = 0; nt < 8; nt++)
#pragma unroll
            for (int i = 0; i < 4; i++) acc[mt][nt][i] = 0.0f;

    // per-lane ldmatrix source offsets (element units)
    const int a_row = warp_m * 32 + (lane & 15);
    const int a_colb = (lane >> 4) << 3;
    const int b_row = warp_n * 64 + (lane & 7) + ((lane >> 4) << 3);
    const int b_colb = ((lane >> 3) & 1) << 3;

    auto stage_copy = [&](int s, int ci) {
        const int ph = ci / nkc;
        const int kc = ci - ph * nkc;
        const int aoff = ((ph == 2) ? K : 0) + kc * 32;
        const int boff = ((ph == 1) ? K : 0) + kc * 32;
        const uint32_t sa = sbase + (uint32_t)s * TILE_BYTES;
        const uint32_t sb = sbase + (uint32_t)(3 + s) * TILE_BYTES;
#pragma unroll
        for (int j = 0; j < 2; j++) {
            const int r = cr0 + 64 * j;
            const uint32_t so = (uint32_t)r * (LDS_STRIDE * 2) + (uint32_t)cc * 16u;
            cp_async16(sa + so, A + (long)(row0 + r) * lda + aoff + cc * 8);
            cp_async16(sb + so, B + (long)(col0 + r) * lda + boff + cc * 8);
        }
        cp_commit();
    };

    // prologue: 2 chunks in flight
    stage_copy(0, 0);
    stage_copy(1, 1);

    for (int ci = 0; ci < nc; ci++) {
        cp_wait<1>();
        __syncthreads();
        // buffer (ci-1)%3 == (ci+2)%3 was finished by ALL warps before this
        // barrier, so it is safe to start the next copy into it now.
        if (ci + 2 < nc) stage_copy((ci + 2) % 3, ci + 2);
        else             cp_commit();   // keep group count advancing for wait<1>

        const int s = ci % 3;
        const uint32_t au = sbase + (uint32_t)s * TILE_BYTES;
        const uint32_t bu = sbase + (uint32_t)(3 + s) * TILE_BYTES;
#pragma unroll
        for (int kk = 0; kk < 2; kk++) {
            uint32_t afr[2][4];
#pragma unroll
            for (int mt = 0; mt < 2; mt++) {
                const uint32_t addr = au +
                    (uint32_t)(a_row + mt * 16) * (LDS_STRIDE * 2) +
                    (uint32_t)(kk * 16 + a_colb) * 2;
                ldsm_x4(afr[mt], addr);
            }
            uint32_t bfr[8][2];
#pragma unroll
            for (int nt2 = 0; nt2 < 4; nt2++) {
                uint32_t r4[4];
                const uint32_t addr = bu +
                    (uint32_t)(b_row + nt2 * 16) * (LDS_STRIDE * 2) +
                    (uint32_t)(kk * 16 + b_colb) * 2;
                ldsm_x4(r4, addr);
                bfr[2 * nt2][0] = r4[0]; bfr[2 * nt2][1] = r4[1];
                bfr[2 * nt2 + 1][0] = r4[2]; bfr[2 * nt2 + 1][1] = r4[3];
            }
#pragma unroll
            for (int mt = 0; mt < 2; mt++)
#pragma unroll
                for (int nt = 0; nt < 8; nt++)
                    mma_bf16(acc[mt][nt], afr[mt], bfr[nt]);
        }
    }

    // ---- epilogue ----
    const int er0 = row0 + warp_m * 32 + (lane >> 2);
    const int ec0 = col0 + warp_n * 64 + (lane & 3) * 2;
#pragma unroll
    for (int mt = 0; mt < 2; mt++) {
#pragma unroll
        for (int nt = 0; nt < 8; nt++) {
            const int r0 = er0 + mt * 16;
            const int r1 = r0 + 8;
            const int c  = ec0 + nt * 8;
            if (MODE == 0) {
                float2 v0, v1;
                v0.x = acc[mt][nt][0]; v0.y = acc[mt][nt][1];
                v1.x = acc[mt][nt][2]; v1.y = acc[mt][nt][3];
                *reinterpret_cast<float2*>(Cf + bz * sC + (long)r0 * ldc + c) = v0;
                *reinterpret_cast<float2*>(Cf + bz * sC + (long)r1 * ldc + c) = v1;
            } else {
                const float b0 = bias[c], b1 = bias[c + 1];
                __nv_bfloat16 h0, h1, l0, l1;
                u16* q0 = Cs + (long)r0 * ldc + c;
                split2(acc[mt][nt][0] + b0, h0, l0);
                split2(acc[mt][nt][1] + b1, h1, l1);
                *reinterpret_cast<__nv_bfloat162*>(q0) = __halves2bfloat162(h0, h1);
                *reinterpret_cast<__nv_bfloat162*>(q0 + loOff) = __halves2bfloat162(l0, l1);
                u16* q1 = Cs + (long)r1 * ldc + c;
                split2(acc[mt][nt][2] + b0, h0, l0);
                split2(acc[mt][nt][3] + b1, h1, l1);
                *reinterpret_cast<__nv_bfloat162*>(q1) = __halves2bfloat162(h0, h1);
                *reinterpret_cast<__nv_bfloat162*>(q1 + loOff) = __halves2bfloat162(l0, l1);
            }
        }
    }
}

// ======================= softmax + split ====================================
__global__ void __launch_bounds__(256)
softmax512_split_kernel(const float* __restrict__ S, u16* __restrict__ P)
{
    __shared__ float red[256];
    const float* row = S + (long)blockIdx.x * 512;
    u16* prow = P + (long)blockIdx.x * 1024;
    const int t = threadIdx.x;

    const float a = row[t];
    const float b = row[t + 256];

    red[t] = fmaxf(a, b);
    __syncthreads();
#pragma unroll
    for (int s = 128; s > 0; s >>= 1) {
        if (t < s) red[t] = fmaxf(red[t], red[t + s]);
        __syncthreads();
    }
    const float mx = red[0];
    __syncthreads();

    const float e0 = __expf(a - mx);
    const float e1 = __expf(b - mx);
    red[t] = e0 + e1;
    __syncthreads();
#pragma unroll
    for (int s = 128; s > 0; s >>= 1) {
        if (t < s) red[t] += red[t + s];
        __syncthreads();
    }
    const float inv = 1.0f / red[0];

    __nv_bfloat16 h, l;
    split2(e0 * inv, h, l);
    *reinterpret_cast<__nv_bfloat16*>(&prow[t])             = h;
    *reinterpret_cast<__nv_bfloat16*>(&prow[512 + t])       = l;
    split2(e1 * inv, h, l);
    *reinterpret_cast<__nv_bfloat16*>(&prow[t + 256])       = h;
    *reinterpret_cast<__nv_bfloat16*>(&prow[512 + t + 256]) = l;
}

// ======================= launch =============================================
extern "C" void kernel_launch(void* const* d_in, const int* in_sizes, int n_in,
                              void* d_out, int out_size)
{
    const float* ix = (const float*)d_in[0];   // [32, 512, 1024]
    const float* io = (const float*)d_in[1];   // [32, 512, 1024]
    const float* W  = (const float*)d_in[2];   // [1024, 1024]
    const float* bi = (const float*)d_in[3];   // [1024]
    float* out = (float*)d_out;                // [32, 512, 1024]

    u16 *ixs, *ios, *iosT, *ws, *exs, *eos, *ps;
    float* sc;
    cudaGetSymbolAddress((void**)&ixs,  g_ixs);
    cudaGetSymbolAddress((void**)&ios,  g_ios);
    cudaGetSymbolAddress((void**)&iosT, g_iosT);
    cudaGetSymbolAddress((void**)&ws,   g_ws);
    cudaGetSymbolAddress((void**)&exs,  g_exs);
    cudaGetSymbolAddress((void**)&eos,  g_eos);
    cudaGetSymbolAddress((void**)&sc,   g_sc);
    cudaGetSymbolAddress((void**)&ps,   g_ps);

    cudaFuncSetAttribute(gemm_mma<0>, cudaFuncAttributeMaxDynamicSharedMemorySize, GEMM_SMEM);
    cudaFuncSetAttribute(gemm_mma<1>, cudaFuncAttributeMaxDynamicSharedMemorySize, GEMM_SMEM);

    const int Bn = 32, L = 512, D = 1024;
    const int Mproj = Bn * L;  // 16384

    // 0) splits
    split_kernel<<<(Mproj * (long)D) / 1024, 256>>>(ix, ixs, D);
    split_kernel<<<(Mproj * (long)D) / 1024, 256>>>(io, ios, D);
    split_kernel<<<(D * (long)D) / 1024, 256>>>(W, ws, D);
    {
        dim3 g(D / 32, L / 32, Bn);
        transpose_split_kernel<<<g, 256>>>(io, iosT);
    }

    // 1) projections -> split outputs (bias fused)
    {
        dim3 g(D / 128, Mproj / 128, 1);
        gemm_mma<1><<<g, 256, GEMM_SMEM>>>(ixs, ws, bi, nullptr, exs, D, 0, 0, 0, 2 * D, D);
        gemm_mma<1><<<g, 256, GEMM_SMEM>>>(ios, ws, bi, nullptr, eos, D, 0, 0, 0, 2 * D, D);
    }

    // 2) scores: S[b] = ex[b] @ eo[b]^T   (fp32 out)
    {
        dim3 g(L / 128, L / 128, Bn);
        gemm_mma<0><<<g, 256, GEMM_SMEM>>>(exs, eos, nullptr, sc, nullptr,
                                           D, (long)L * 2 * D, (long)L * 2 * D,
                                           (long)L * L, L, 0);
    }

    // 3) softmax + split probs
    softmax512_split_kernel<<<Bn * L, 256>>>(sc, ps);

    // 4) out[b] = P[b] @ ioT[b]^T  (NT with pre-transposed io)
    {
        dim3 g(D / 128, L / 128, Bn);
        gemm_mma<0><<<g, 256, GEMM_SMEM>>>(ps, iosT, nullptr, out, nullptr,
                                           L, (long)L * 2 * L, (long)D * 2 * L,
                                           (long)L * D, D, 0);
    }
}

// round 6
// speedup vs baseline: 2.2059x; 1.0234x over previous
#include <cuda_runtime.h>
#include <cuda_bf16.h>
#include <cstdint>

// ---------------------------------------------------------------------------
// Aligner via mma.sync bf16 (HMMA tensor pipe) with 2-term hi/lo split.
//   ex = ix@W^T+b ; eo = io@W^T+b ; S = ex@eo^T ; P = softmax(S); out = P@io
// fp32 GEMM == 3 bf16 phases accumulated in fp32 registers:
//   A_hi*B_hi + A_hi*B_lo + A_lo*B_hi
// R5: 4 warps x (64x64) warp tiles (128 threads), 3-stage cp.async, 2 CTA/SM.
// ---------------------------------------------------------------------------

typedef unsigned short u16;  // raw bf16 bits

// ======================= scratch (device globals) ===========================
__device__ u16   g_ixs [16384L * 2048];     // ix split  [M, hi(0..1023)|lo]
__device__ u16   g_ios [16384L * 2048];     // io split
__device__ u16   g_iosT[32L * 1024 * 1024]; // io^T split per batch [d, m_hi|m_lo]
__device__ u16   g_ws  [1024L * 2048];      // W split
__device__ u16   g_exs [16384L * 2048];     // ex split (proj output)
__device__ u16   g_eos [16384L * 2048];     // eo split
__device__ float g_sc  [32L * 512 * 512];   // scores fp32
__device__ u16   g_ps  [32L * 512 * 1024];  // softmax probs split [l, m_hi|m_lo]

// ======================= PTX helpers ========================================
__device__ __forceinline__ uint32_t smem_u32(const void* p) {
    uint32_t a;
    asm("{ .reg .u64 t; cvta.to.shared.u64 t, %1; cvt.u32.u64 %0, t; }"
        : "=r"(a) : "l"(p));
    return a;
}

__device__ __forceinline__ void cp_async16(uint32_t saddr, const void* gaddr) {
    asm volatile("cp.async.cg.shared.global [%0], [%1], 16;"
                 :: "r"(saddr), "l"(gaddr) : "memory");
}
__device__ __forceinline__ void cp_commit() {
    asm volatile("cp.async.commit_group;" ::: "memory");
}
template <int N>
__device__ __forceinline__ void cp_wait() {
    asm volatile("cp.async.wait_group %0;" :: "n"(N) : "memory");
}

__device__ __forceinline__ void ldsm_x4(uint32_t* r, uint32_t addr) {
    asm volatile("ldmatrix.sync.aligned.m8n8.x4.shared.b16 {%0,%1,%2,%3}, [%4];"
                 : "=r"(r[0]), "=r"(r[1]), "=r"(r[2]), "=r"(r[3]) : "r"(addr));
}

__device__ __forceinline__ void mma_bf16(float* c, const uint32_t* a,
                                         const uint32_t* b) {
    asm volatile(
        "mma.sync.aligned.m16n8k16.row.col.f32.bf16.bf16.f32 "
        "{%0,%1,%2,%3}, {%4,%5,%6,%7}, {%8,%9}, {%0,%1,%2,%3};"
        : "+f"(c[0]), "+f"(c[1]), "+f"(c[2]), "+f"(c[3])
        : "r"(a[0]), "r"(a[1]), "r"(a[2]), "r"(a[3]), "r"(b[0]), "r"(b[1]));
}

// ======================= split helpers ======================================
__device__ __forceinline__ void split2(float v, __nv_bfloat16& h, __nv_bfloat16& l) {
    h = __float2bfloat16(v);
    l = __float2bfloat16(v - __bfloat162float(h));
}

// fp32 [R, C] -> bf16 [R, 2C] (hi | lo). One float4 per thread.
__global__ void __launch_bounds__(256)
split_kernel(const float* __restrict__ in, u16* __restrict__ out, int C)
{
    const long idx = (long)blockIdx.x * 256 + threadIdx.x;
    const long e = idx * 4;
    const long r = e / C;
    const int  c = (int)(e - r * C);
    const float4 v = *reinterpret_cast<const float4*>(in + e);
    __nv_bfloat16 h0, h1, h2, h3, l0, l1, l2, l3;
    split2(v.x, h0, l0); split2(v.y, h1, l1); split2(v.z, h2, l2); split2(v.w, h3, l3);
    __nv_bfloat16* oh = reinterpret_cast<__nv_bfloat16*>(out + r * (2L * C) + c);
    __nv_bfloat16* ol = reinterpret_cast<__nv_bfloat16*>(out + r * (2L * C) + C + c);
    *reinterpret_cast<__nv_bfloat162*>(oh)     = __halves2bfloat162(h0, h1);
    *reinterpret_cast<__nv_bfloat162*>(oh + 2) = __halves2bfloat162(h2, h3);
    *reinterpret_cast<__nv_bfloat162*>(ol)     = __halves2bfloat162(l0, l1);
    *reinterpret_cast<__nv_bfloat162*>(ol + 2) = __halves2bfloat162(l2, l3);
}

// io [32,512,1024] fp32 -> ioT split [32,1024, 512hi|512lo] bf16
__global__ void __launch_bounds__(256)
transpose_split_kernel(const float* __restrict__ in, u16* __restrict__ out)
{
    __shared__ float t[32][33];
    const int b  = blockIdx.z;
    const int d0 = blockIdx.x * 32;
    const int m0 = blockIdx.y * 32;
    const int tx = threadIdx.x & 31;
    const int ty = threadIdx.x >> 5;   // 0..7
    const float* ib = in + (long)b * 512 * 1024;
#pragma unroll
    for (int i = 0; i < 4; i++)
        t[ty + 8 * i][tx] = ib[(long)(m0 + ty + 8 * i) * 1024 + d0 + tx];
    __syncthreads();
    u16* ob = out + (long)b * 1024 * 1024;
#pragma unroll
    for (int i = 0; i < 4; i++) {
        const int d = d0 + ty + 8 * i;
        const int m = m0 + tx;
        __nv_bfloat16 h, l;
        split2(t[tx][ty + 8 * i], h, l);
        *reinterpret_cast<__nv_bfloat16*>(&ob[(long)d * 1024 + m])       = h;
        *reinterpret_cast<__nv_bfloat16*>(&ob[(long)d * 1024 + 512 + m]) = l;
    }
}

// ======================= mma.sync GEMM ======================================
// C[M,N] = A[M, 2K] (*) B[N, 2K]  via 3 bf16 phases, fp32 reg accumulate.
// CTA tile 128x128, BK=32, 4 warps (2Mx2N grid, warp tile 64x64).
// 3-stage cp.async pipeline, 1 __syncthreads per chunk, 2 CTAs/SM.
// MODE 0: fp32 out to Cf;  MODE 1: bias add + re-split to Cs (hi|lo at loOff).
#define LDS_STRIDE 40                        // 32 + 8 pad elements per row
#define TILE_BYTES (128 * LDS_STRIDE * 2)    // 10240 B per tile per stage
#define GEMM_SMEM (6 * TILE_BYTES)           // 3 stages x (A + B) = 61440 B

template <int MODE>
__global__ void __launch_bounds__(128, 2)
gemm_mma(const u16* __restrict__ A, const u16* __restrict__ B,
         const float* __restrict__ bias, float* __restrict__ Cf,
         u16* __restrict__ Cs,
         int K, long sA, long sB, long sC, int ldc, int loOff)
{
    extern __shared__ char dynsmem[];

    const int tid  = threadIdx.x;
    const int wid  = tid >> 5;
    const int lane = tid & 31;

    const long bz = blockIdx.z;
    A += bz * sA;
    B += bz * sB;
    const int row0 = blockIdx.y * 128;
    const int col0 = blockIdx.x * 128;
    const long lda = 2L * K;

    const int nkc = K / 32;
    const int nc  = 3 * nkc;

    const uint32_t sbase = smem_u32(dynsmem);
    // stage s: A tile at sbase + s*TILE_BYTES, B tile at sbase + (3+s)*TILE_BYTES

    // copy mapping: vector v = tid + 128*j (j=0..3); row = v>>2, 16B col = v&3
    const int cr0 = tid >> 2;     // 0..31
    const int cc  = tid & 3;

    // warp tiling: 2x2 grid of 64x64 warp tiles
    const int warp_m = wid & 1;
    const int warp_n = wid >> 1;

    float acc[4][8][4];
#pragma unroll
    for (int mt = 0; mt < 4; mt++)
#pragma unroll
        for (int nt = 0; nt < 8; nt++)
#pragma unroll
            for (int i = 0; i < 4; i++) acc[mt][nt][i] = 0.0f;

    // per-lane ldmatrix source offsets (element units)
    const int a_row = warp_m * 64 + (lane & 15);
    const int a_colb = (lane >> 4) << 3;
    const int b_row = warp_n * 64 + (lane & 7) + ((lane >> 4) << 3);
    const int b_colb = ((lane >> 3) & 1) << 3;

    auto stage_copy = [&](int s, int ci) {
        const int ph = ci / nkc;
        const int kc = ci - ph * nkc;
        const int aoff = ((ph == 2) ? K : 0) + kc * 32;
        const int boff = ((ph == 1) ? K : 0) + kc * 32;
        const uint32_t sa = sbase + (uint32_t)s * TILE_BYTES;
        const uint32_t sb = sbase + (uint32_t)(3 + s) * TILE_BYTES;
#pragma unroll
        for (int j = 0; j < 4; j++) {
            const int r = cr0 + 32 * j;
            const uint32_t so = (uint32_t)r * (LDS_STRIDE * 2) + (uint32_t)cc * 16u;
            cp_async16(sa + so, A + (long)(row0 + r) * lda + aoff + cc * 8);
            cp_async16(sb + so, B + (long)(col0 + r) * lda + boff + cc * 8);
        }
        cp_commit();
    };

    // prologue: 2 chunks in flight
    stage_copy(0, 0);
    stage_copy(1, 1);

    for (int ci = 0; ci < nc; ci++) {
        cp_wait<1>();
        __syncthreads();
        // buffer (ci+2)%3 was finished by ALL warps before this barrier.
        if (ci + 2 < nc) stage_copy((ci + 2) % 3, ci + 2);
        else             cp_commit();   // keep group count advancing for wait<1>

        const int s = ci % 3;
        const uint32_t au = sbase + (uint32_t)s * TILE_BYTES;
        const uint32_t bu = sbase + (uint32_t)(3 + s) * TILE_BYTES;
#pragma unroll
        for (int kk = 0; kk < 2; kk++) {
            uint32_t afr[4][4];
#pragma unroll
            for (int mt = 0; mt < 4; mt++) {
                const uint32_t addr = au +
                    (uint32_t)(a_row + mt * 16) * (LDS_STRIDE * 2) +
                    (uint32_t)(kk * 16 + a_colb) * 2;
                ldsm_x4(afr[mt], addr);
            }
            uint32_t bfr[8][2];
#pragma unroll
            for (int nt2 = 0; nt2 < 4; nt2++) {
                uint32_t r4[4];
                const uint32_t addr = bu +
                    (uint32_t)(b_row + nt2 * 16) * (LDS_STRIDE * 2) +
                    (uint32_t)(kk * 16 + b_colb) * 2;
                ldsm_x4(r4, addr);
                bfr[2 * nt2][0] = r4[0]; bfr[2 * nt2][1] = r4[1];
                bfr[2 * nt2 + 1][0] = r4[2]; bfr[2 * nt2 + 1][1] = r4[3];
            }
#pragma unroll
            for (int mt = 0; mt < 4; mt++)
#pragma unroll
                for (int nt = 0; nt < 8; nt++)
                    mma_bf16(acc[mt][nt], afr[mt], bfr[nt]);
        }
    }

    // ---- epilogue ----
    const int er0 = row0 + warp_m * 64 + (lane >> 2);
    const int ec0 = col0 + warp_n * 64 + (lane & 3) * 2;
#pragma unroll
    for (int mt = 0; mt < 4; mt++) {
#pragma unroll
        for (int nt = 0; nt < 8; nt++) {
            const int r0 = er0 + mt * 16;
            const int r1 = r0 + 8;
            const int c  = ec0 + nt * 8;
            if (MODE == 0) {
                float2 v0, v1;
                v0.x = acc[mt][nt][0]; v0.y = acc[mt][nt][1];
                v1.x = acc[mt][nt][2]; v1.y = acc[mt][nt][3];
                *reinterpret_cast<float2*>(Cf + bz * sC + (long)r0 * ldc + c) = v0;
                *reinterpret_cast<float2*>(Cf + bz * sC + (long)r1 * ldc + c) = v1;
            } else {
                const float b0 = bias[c], b1 = bias[c + 1];
                __nv_bfloat16 h0, h1, l0, l1;
                u16* q0 = Cs + (long)r0 * ldc + c;
                split2(acc[mt][nt][0] + b0, h0, l0);
                split2(acc[mt][nt][1] + b1, h1, l1);
                *reinterpret_cast<__nv_bfloat162*>(q0) = __halves2bfloat162(h0, h1);
                *reinterpret_cast<__nv_bfloat162*>(q0 + loOff) = __halves2bfloat162(l0, l1);
                u16* q1 = Cs + (long)r1 * ldc + c;
                split2(acc[mt][nt][2] + b0, h0, l0);
                split2(acc[mt][nt][3] + b1, h1, l1);
                *reinterpret_cast<__nv_bfloat162*>(q1) = __halves2bfloat162(h0, h1);
                *reinterpret_cast<__nv_bfloat162*>(q1 + loOff) = __halves2bfloat162(l0, l1);
            }
        }
    }
}

// ======================= softmax + split ====================================
__global__ void __launch_bounds__(256)
softmax512_split_kernel(const float* __restrict__ S, u16* __restrict__ P)
{
    __shared__ float red[256];
    const float* row = S + (long)blockIdx.x * 512;
    u16* prow = P + (long)blockIdx.x * 1024;
    const int t = threadIdx.x;

    const float a = row[t];
    const float b = row[t + 256];

    red[t] = fmaxf(a, b);
    __syncthreads();
#pragma unroll
    for (int s = 128; s > 0; s >>= 1) {
        if (t < s) red[t] = fmaxf(red[t], red[t + s]);
        __syncthreads();
    }
    const float mx = red[0];
    __syncthreads();

    const float e0 = __expf(a - mx);
    const float e1 = __expf(b - mx);
    red[t] = e0 + e1;
    __syncthreads();
#pragma unroll
    for (int s = 128; s > 0; s >>= 1) {
        if (t < s) red[t] += red[t + s];
        __syncthreads();
    }
    const float inv = 1.0f / red[0];

    __nv_bfloat16 h, l;
    split2(e0 * inv, h, l);
    *reinterpret_cast<__nv_bfloat16*>(&prow[t])             = h;
    *reinterpret_cast<__nv_bfloat16*>(&prow[512 + t])       = l;
    split2(e1 * inv, h, l);
    *reinterpret_cast<__nv_bfloat16*>(&prow[t + 256])       = h;
    *reinterpret_cast<__nv_bfloat16*>(&prow[512 + t + 256]) = l;
}

// ======================= launch =============================================
extern "C" void kernel_launch(void* const* d_in, const int* in_sizes, int n_in,
                              void* d_out, int out_size)
{
    const float* ix = (const float*)d_in[0];   // [32, 512, 1024]
    const float* io = (const float*)d_in[1];   // [32, 512, 1024]
    const float* W  = (const float*)d_in[2];   // [1024, 1024]
    const float* bi = (const float*)d_in[3];   // [1024]
    float* out = (float*)d_out;                // [32, 512, 1024]

    u16 *ixs, *ios, *iosT, *ws, *exs, *eos, *ps;
    float* sc;
    cudaGetSymbolAddress((void**)&ixs,  g_ixs);
    cudaGetSymbolAddress((void**)&ios,  g_ios);
    cudaGetSymbolAddress((void**)&iosT, g_iosT);
    cudaGetSymbolAddress((void**)&ws,   g_ws);
    cudaGetSymbolAddress((void**)&exs,  g_exs);
    cudaGetSymbolAddress((void**)&eos,  g_eos);
    cudaGetSymbolAddress((void**)&sc,   g_sc);
    cudaGetSymbolAddress((void**)&ps,   g_ps);

    cudaFuncSetAttribute(gemm_mma<0>, cudaFuncAttributeMaxDynamicSharedMemorySize, GEMM_SMEM);
    cudaFuncSetAttribute(gemm_mma<1>, cudaFuncAttributeMaxDynamicSharedMemorySize, GEMM_SMEM);

    const int Bn = 32, L = 512, D = 1024;
    const int Mproj = Bn * L;  // 16384

    // 0) splits
    split_kernel<<<(Mproj * (long)D) / 1024, 256>>>(ix, ixs, D);
    split_kernel<<<(Mproj * (long)D) / 1024, 256>>>(io, ios, D);
    split_kernel<<<(D * (long)D) / 1024, 256>>>(W, ws, D);
    {
        dim3 g(D / 32, L / 32, Bn);
        transpose_split_kernel<<<g, 256>>>(io, iosT);
    }

    // 1) projections -> split outputs (bias fused)
    {
        dim3 g(D / 128, Mproj / 128, 1);
        gemm_mma<1><<<g, 128, GEMM_SMEM>>>(ixs, ws, bi, nullptr, exs, D, 0, 0, 0, 2 * D, D);
        gemm_mma<1><<<g, 128, GEMM_SMEM>>>(ios, ws, bi, nullptr, eos, D, 0, 0, 0, 2 * D, D);
    }

    // 2) scores: S[b] = ex[b] @ eo[b]^T   (fp32 out)
    {
        dim3 g(L / 128, L / 128, Bn);
        gemm_mma<0><<<g, 128, GEMM_SMEM>>>(exs, eos, nullptr, sc, nullptr,
                                           D, (long)L * 2 * D, (long)L * 2 * D,
                                           (long)L * L, L, 0);
    }

    // 3) softmax + split probs
    softmax512_split_kernel<<<Bn * L, 256>>>(sc, ps);

    // 4) out[b] = P[b] @ ioT[b]^T  (NT with pre-transposed io)
    {
        dim3 g(D / 128, L / 128, Bn);
        gemm_mma<0><<<g, 128, GEMM_SMEM>>>(ps, iosT, nullptr, out, nullptr,
                                           L, (long)L * 2 * L, (long)D * 2 * L,
                                           (long)L * D, D, 0);
    }
}

// round 7
// speedup vs baseline: 2.5438x; 1.1532x over previous
#include <cuda_runtime.h>
#include <cuda_bf16.h>
#include <cstdint>

// ---------------------------------------------------------------------------
// Aligner via mma.sync bf16 (HMMA) with 2-term hi/lo split.
//   ex = ix@W^T+b ; eo = io@W^T+b ; S = ex@eo^T ; P = softmax(S); out = P@io
// fp32 GEMM == 3 bf16 phases accumulated in fp32 registers:
//   A_hi*B_hi + A_hi*B_lo + A_lo*B_hi
// R6: per k-chunk load Ah,Al,Bh,Bl ONCE and run all 3 phases on resident
//     tiles (L2 traffic x2/3, barriers /3). 2-stage pipeline, 2 CTA/SM.
// ---------------------------------------------------------------------------

typedef unsigned short u16;  // raw bf16 bits

// ======================= scratch (device globals) ===========================
__device__ u16   g_ixs [16384L * 2048];     // ix split  [M, hi(0..1023)|lo]
__device__ u16   g_ios [16384L * 2048];     // io split
__device__ u16   g_iosT[32L * 1024 * 1024]; // io^T split per batch [d, m_hi|m_lo]
__device__ u16   g_ws  [1024L * 2048];      // W split
__device__ u16   g_exs [16384L * 2048];     // ex split (proj output)
__device__ u16   g_eos [16384L * 2048];     // eo split
__device__ float g_sc  [32L * 512 * 512];   // scores fp32
__device__ u16   g_ps  [32L * 512 * 1024];  // softmax probs split [l, m_hi|m_lo]

// ======================= PTX helpers ========================================
__device__ __forceinline__ uint32_t smem_u32(const void* p) {
    uint32_t a;
    asm("{ .reg .u64 t; cvta.to.shared.u64 t, %1; cvt.u32.u64 %0, t; }"
        : "=r"(a) : "l"(p));
    return a;
}

__device__ __forceinline__ void cp_async16(uint32_t saddr, const void* gaddr) {
    asm volatile("cp.async.cg.shared.global [%0], [%1], 16;"
                 :: "r"(saddr), "l"(gaddr) : "memory");
}
__device__ __forceinline__ void cp_commit() {
    asm volatile("cp.async.commit_group;" ::: "memory");
}
template <int N>
__device__ __forceinline__ void cp_wait() {
    asm volatile("cp.async.wait_group %0;" :: "n"(N) : "memory");
}

__device__ __forceinline__ void ldsm_x4(uint32_t* r, uint32_t addr) {
    asm volatile("ldmatrix.sync.aligned.m8n8.x4.shared.b16 {%0,%1,%2,%3}, [%4];"
                 : "=r"(r[0]), "=r"(r[1]), "=r"(r[2]), "=r"(r[3]) : "r"(addr));
}

__device__ __forceinline__ void mma_bf16(float* c, const uint32_t* a,
                                         const uint32_t* b) {
    asm volatile(
        "mma.sync.aligned.m16n8k16.row.col.f32.bf16.bf16.f32 "
        "{%0,%1,%2,%3}, {%4,%5,%6,%7}, {%8,%9}, {%0,%1,%2,%3};"
        : "+f"(c[0]), "+f"(c[1]), "+f"(c[2]), "+f"(c[3])
        : "r"(a[0]), "r"(a[1]), "r"(a[2]), "r"(a[3]), "r"(b[0]), "r"(b[1]));
}

// ======================= split helpers ======================================
__device__ __forceinline__ void split2(float v, __nv_bfloat16& h, __nv_bfloat16& l) {
    h = __float2bfloat16(v);
    l = __float2bfloat16(v - __bfloat162float(h));
}

// fp32 [R, C] -> bf16 [R, 2C] (hi | lo). One float4 per thread.
__global__ void __launch_bounds__(256)
split_kernel(const float* __restrict__ in, u16* __restrict__ out, int C)
{
    const long idx = (long)blockIdx.x * 256 + threadIdx.x;
    const long e = idx * 4;
    const long r = e / C;
    const int  c = (int)(e - r * C);
    const float4 v = *reinterpret_cast<const float4*>(in + e);
    __nv_bfloat16 h0, h1, h2, h3, l0, l1, l2, l3;
    split2(v.x, h0, l0); split2(v.y, h1, l1); split2(v.z, h2, l2); split2(v.w, h3, l3);
    __nv_bfloat16* oh = reinterpret_cast<__nv_bfloat16*>(out + r * (2L * C) + c);
    __nv_bfloat16* ol = reinterpret_cast<__nv_bfloat16*>(out + r * (2L * C) + C + c);
    *reinterpret_cast<__nv_bfloat162*>(oh)     = __halves2bfloat162(h0, h1);
    *reinterpret_cast<__nv_bfloat162*>(oh + 2) = __halves2bfloat162(h2, h3);
    *reinterpret_cast<__nv_bfloat162*>(ol)     = __halves2bfloat162(l0, l1);
    *reinterpret_cast<__nv_bfloat162*>(ol + 2) = __halves2bfloat162(l2, l3);
}

// io [32,512,1024] fp32 -> ioT split [32,1024, 512hi|512lo] bf16
__global__ void __launch_bounds__(256)
transpose_split_kernel(const float* __restrict__ in, u16* __restrict__ out)
{
    __shared__ float t[32][33];
    const int b  = blockIdx.z;
    const int d0 = blockIdx.x * 32;
    const int m0 = blockIdx.y * 32;
    const int tx = threadIdx.x & 31;
    const int ty = threadIdx.x >> 5;   // 0..7
    const float* ib = in + (long)b * 512 * 1024;
#pragma unroll
    for (int i = 0; i < 4; i++)
        t[ty + 8 * i][tx] = ib[(long)(m0 + ty + 8 * i) * 1024 + d0 + tx];
    __syncthreads();
    u16* ob = out + (long)b * 1024 * 1024;
#pragma unroll
    for (int i = 0; i < 4; i++) {
        const int d = d0 + ty + 8 * i;
        const int m = m0 + tx;
        __nv_bfloat16 h, l;
        split2(t[tx][ty + 8 * i], h, l);
        *reinterpret_cast<__nv_bfloat16*>(&ob[(long)d * 1024 + m])       = h;
        *reinterpret_cast<__nv_bfloat16*>(&ob[(long)d * 1024 + 512 + m]) = l;
    }
}

// ======================= mma.sync GEMM ======================================
// C[M,N] = A[M, 2K] (*) B[N, 2K]  via 3 bf16 phases, fp32 reg accumulate.
// CTA tile 128x128, k-chunk 32, 4 warps (2Mx2N grid, warp tile 64x64).
// Per chunk: load Ah/Al/Bh/Bl tiles once; 3 phase MMA groups on resident smem.
// 2-stage cp.async pipeline. 2 CTAs/SM.
// MODE 0: fp32 out to Cf;  MODE 1: bias add + re-split to Cs (hi|lo at loOff).
#define LDS_STRIDE 40                        // 32 + 8 pad elements per row
#define TILE_BYTES (128 * LDS_STRIDE * 2)    // 10240 B per tile
#define STAGE_BYTES (4 * TILE_BYTES)         // Ah,Al,Bh,Bl
#define GEMM_SMEM (2 * STAGE_BYTES)          // 2 stages = 81920 B

template <int MODE>
__global__ void __launch_bounds__(128, 2)
gemm_mma(const u16* __restrict__ A, const u16* __restrict__ B,
         const float* __restrict__ bias, float* __restrict__ Cf,
         u16* __restrict__ Cs,
         int K, long sA, long sB, long sC, int ldc, int loOff)
{
    extern __shared__ char dynsmem[];

    const int tid  = threadIdx.x;
    const int wid  = tid >> 5;
    const int lane = tid & 31;

    const long bz = blockIdx.z;
    A += bz * sA;
    B += bz * sB;
    const int row0 = blockIdx.y * 128;
    const int col0 = blockIdx.x * 128;
    const long lda = 2L * K;

    const int nkc = K / 32;

    const uint32_t sbase = smem_u32(dynsmem);
    // stage s: +s*STAGE_BYTES; tiles within stage: 0=Ah 1=Al 2=Bh 3=Bl

    // copy mapping: vector v = tid + 128*j (j=0..3); row = v>>2, 16B col = v&3
    const int cr0 = tid >> 2;     // 0..31
    const int cc  = tid & 3;

    // warp tiling: 2x2 grid of 64x64 warp tiles
    const int warp_m = wid & 1;
    const int warp_n = wid >> 1;

    float acc[4][8][4];
#pragma unroll
    for (int mt = 0; mt < 4; mt++)
#pragma unroll
        for (int nt = 0; nt < 8; nt++)
#pragma unroll
            for (int i = 0; i < 4; i++) acc[mt][nt][i] = 0.0f;

    // per-lane ldmatrix source offsets (element units)
    const int a_row = warp_m * 64 + (lane & 15);
    const int a_colb = (lane >> 4) << 3;
    const int b_row = warp_n * 64 + (lane & 7) + ((lane >> 4) << 3);
    const int b_colb = ((lane >> 3) & 1) << 3;

    auto stage_copy = [&](int s, int kc) {
        const uint32_t sb0 = sbase + (uint32_t)s * STAGE_BYTES;
        const int hoff = kc * 32;
        const int loff = K + kc * 32;
#pragma unroll
        for (int j = 0; j < 4; j++) {
            const int r = cr0 + 32 * j;
            const uint32_t so = (uint32_t)r * (LDS_STRIDE * 2) + (uint32_t)cc * 16u;
            const u16* arow = A + (long)(row0 + r) * lda + cc * 8;
            const u16* brow = B + (long)(col0 + r) * lda + cc * 8;
            cp_async16(sb0 + 0 * TILE_BYTES + so, arow + hoff);
            cp_async16(sb0 + 1 * TILE_BYTES + so, arow + loff);
            cp_async16(sb0 + 2 * TILE_BYTES + so, brow + hoff);
            cp_async16(sb0 + 3 * TILE_BYTES + so, brow + loff);
        }
        cp_commit();
    };

    stage_copy(0, 0);

    for (int kc = 0; kc < nkc; kc++) {
        __syncthreads();   // all warps done reading stage (kc+1)&1 (chunk kc-1)
        if (kc + 1 < nkc) {
            stage_copy((kc + 1) & 1, kc + 1);
            cp_wait<1>();
        } else {
            cp_wait<0>();
        }
        __syncthreads();   // chunk kc data visible to all warps

        const uint32_t st = sbase + (uint32_t)(kc & 1) * STAGE_BYTES;
#pragma unroll
        for (int kk = 0; kk < 2; kk++) {
            const uint32_t a_off =
                (uint32_t)a_row * (LDS_STRIDE * 2) + (uint32_t)(kk * 16 + a_colb) * 2;
            const uint32_t b_off =
                (uint32_t)b_row * (LDS_STRIDE * 2) + (uint32_t)(kk * 16 + b_colb) * 2;

            // ---- load Ah, Bh frags; phase 1: Ah*Bh ----
            uint32_t ah[4][4];
#pragma unroll
            for (int mt = 0; mt < 4; mt++)
                ldsm_x4(ah[mt], st + 0 * TILE_BYTES + a_off +
                                (uint32_t)(mt * 16) * (LDS_STRIDE * 2));
            uint32_t bh[8][2];
#pragma unroll
            for (int nt2 = 0; nt2 < 4; nt2++) {
                uint32_t r4[4];
                ldsm_x4(r4, st + 2 * TILE_BYTES + b_off +
                            (uint32_t)(nt2 * 16) * (LDS_STRIDE * 2));
                bh[2 * nt2][0] = r4[0]; bh[2 * nt2][1] = r4[1];
                bh[2 * nt2 + 1][0] = r4[2]; bh[2 * nt2 + 1][1] = r4[3];
            }
#pragma unroll
            for (int mt = 0; mt < 4; mt++)
#pragma unroll
                for (int nt = 0; nt < 8; nt++)
                    mma_bf16(acc[mt][nt], ah[mt], bh[nt]);

            // ---- load Bl frags; phase 2: Ah*Bl ----
            {
                uint32_t bl[8][2];
#pragma unroll
                for (int nt2 = 0; nt2 < 4; nt2++) {
                    uint32_t r4[4];
                    ldsm_x4(r4, st + 3 * TILE_BYTES + b_off +
                                (uint32_t)(nt2 * 16) * (LDS_STRIDE * 2));
                    bl[2 * nt2][0] = r4[0]; bl[2 * nt2][1] = r4[1];
                    bl[2 * nt2 + 1][0] = r4[2]; bl[2 * nt2 + 1][1] = r4[3];
                }
#pragma unroll
                for (int mt = 0; mt < 4; mt++)
#pragma unroll
                    for (int nt = 0; nt < 8; nt++)
                        mma_bf16(acc[mt][nt], ah[mt], bl[nt]);
            }

            // ---- load Al frags (Ah dead); phase 3: Al*Bh ----
            {
                uint32_t al[4][4];
#pragma unroll
                for (int mt = 0; mt < 4; mt++)
                    ldsm_x4(al[mt], st + 1 * TILE_BYTES + a_off +
                                    (uint32_t)(mt * 16) * (LDS_STRIDE * 2));
#pragma unroll
                for (int mt = 0; mt < 4; mt++)
#pragma unroll
                    for (int nt = 0; nt < 8; nt++)
                        mma_bf16(acc[mt][nt], al[mt], bh[nt]);
            }
        }
    }

    // ---- epilogue ----
    const int er0 = row0 + warp_m * 64 + (lane >> 2);
    const int ec0 = col0 + warp_n * 64 + (lane & 3) * 2;
#pragma unroll
    for (int mt = 0; mt < 4; mt++) {
#pragma unroll
        for (int nt = 0; nt < 8; nt++) {
            const int r0 = er0 + mt * 16;
            const int r1 = r0 + 8;
            const int c  = ec0 + nt * 8;
            if (MODE == 0) {
                float2 v0, v1;
                v0.x = acc[mt][nt][0]; v0.y = acc[mt][nt][1];
                v1.x = acc[mt][nt][2]; v1.y = acc[mt][nt][3];
                *reinterpret_cast<float2*>(Cf + bz * sC + (long)r0 * ldc + c) = v0;
                *reinterpret_cast<float2*>(Cf + bz * sC + (long)r1 * ldc + c) = v1;
            } else {
                const float b0 = bias[c], b1 = bias[c + 1];
                __nv_bfloat16 h0, h1, l0, l1;
                u16* q0 = Cs + (long)r0 * ldc + c;
                split2(acc[mt][nt][0] + b0, h0, l0);
                split2(acc[mt][nt][1] + b1, h1, l1);
                *reinterpret_cast<__nv_bfloat162*>(q0) = __halves2bfloat162(h0, h1);
                *reinterpret_cast<__nv_bfloat162*>(q0 + loOff) = __halves2bfloat162(l0, l1);
                u16* q1 = Cs + (long)r1 * ldc + c;
                split2(acc[mt][nt][2] + b0, h0, l0);
                split2(acc[mt][nt][3] + b1, h1, l1);
                *reinterpret_cast<__nv_bfloat162*>(q1) = __halves2bfloat162(h0, h1);
                *reinterpret_cast<__nv_bfloat162*>(q1 + loOff) = __halves2bfloat162(l0, l1);
            }
        }
    }
}

// ======================= softmax + split ====================================
__global__ void __launch_bounds__(256)
softmax512_split_kernel(const float* __restrict__ S, u16* __restrict__ P)
{
    __shared__ float red[256];
    const float* row = S + (long)blockIdx.x * 512;
    u16* prow = P + (long)blockIdx.x * 1024;
    const int t = threadIdx.x;

    const float a = row[t];
    const float b = row[t + 256];

    red[t] = fmaxf(a, b);
    __syncthreads();
#pragma unroll
    for (int s = 128; s > 0; s >>= 1) {
        if (t < s) red[t] = fmaxf(red[t], red[t + s]);
        __syncthreads();
    }
    const float mx = red[0];
    __syncthreads();

    const float e0 = __expf(a - mx);
    const float e1 = __expf(b - mx);
    red[t] = e0 + e1;
    __syncthreads();
#pragma unroll
    for (int s = 128; s > 0; s >>= 1) {
        if (t < s) red[t] += red[t + s];
        __syncthreads();
    }
    const float inv = 1.0f / red[0];

    __nv_bfloat16 h, l;
    split2(e0 * inv, h, l);
    *reinterpret_cast<__nv_bfloat16*>(&prow[t])             = h;
    *reinterpret_cast<__nv_bfloat16*>(&prow[512 + t])       = l;
    split2(e1 * inv, h, l);
    *reinterpret_cast<__nv_bfloat16*>(&prow[t + 256])       = h;
    *reinterpret_cast<__nv_bfloat16*>(&prow[512 + t + 256]) = l;
}

// ======================= launch =============================================
extern "C" void kernel_launch(void* const* d_in, const int* in_sizes, int n_in,
                              void* d_out, int out_size)
{
    const float* ix = (const float*)d_in[0];   // [32, 512, 1024]
    const float* io = (const float*)d_in[1];   // [32, 512, 1024]
    const float* W  = (const float*)d_in[2];   // [1024, 1024]
    const float* bi = (const float*)d_in[3];   // [1024]
    float* out = (float*)d_out;                // [32, 512, 1024]

    u16 *ixs, *ios, *iosT, *ws, *exs, *eos, *ps;
    float* sc;
    cudaGetSymbolAddress((void**)&ixs,  g_ixs);
    cudaGetSymbolAddress((void**)&ios,  g_ios);
    cudaGetSymbolAddress((void**)&iosT, g_iosT);
    cudaGetSymbolAddress((void**)&ws,   g_ws);
    cudaGetSymbolAddress((void**)&exs,  g_exs);
    cudaGetSymbolAddress((void**)&eos,  g_eos);
    cudaGetSymbolAddress((void**)&sc,   g_sc);
    cudaGetSymbolAddress((void**)&ps,   g_ps);

    cudaFuncSetAttribute(gemm_mma<0>, cudaFuncAttributeMaxDynamicSharedMemorySize, GEMM_SMEM);
    cudaFuncSetAttribute(gemm_mma<1>, cudaFuncAttributeMaxDynamicSharedMemorySize, GEMM_SMEM);

    const int Bn = 32, L = 512, D = 1024;
    const int Mproj = Bn * L;  // 16384

    // 0) splits
    split_kernel<<<(Mproj * (long)D) / 1024, 256>>>(ix, ixs, D);
    split_kernel<<<(Mproj * (long)D) / 1024, 256>>>(io, ios, D);
    split_kernel<<<(D * (long)D) / 1024, 256>>>(W, ws, D);
    {
        dim3 g(D / 32, L / 32, Bn);
        transpose_split_kernel<<<g, 256>>>(io, iosT);
    }

    // 1) projections -> split outputs (bias fused)
    {
        dim3 g(D / 128, Mproj / 128, 1);
        gemm_mma<1><<<g, 128, GEMM_SMEM>>>(ixs, ws, bi, nullptr, exs, D, 0, 0, 0, 2 * D, D);
        gemm_mma<1><<<g, 128, GEMM_SMEM>>>(ios, ws, bi, nullptr, eos, D, 0, 0, 0, 2 * D, D);
    }

    // 2) scores: S[b] = ex[b] @ eo[b]^T   (fp32 out)
    {
        dim3 g(L / 128, L / 128, Bn);
        gemm_mma<0><<<g, 128, GEMM_SMEM>>>(exs, eos, nullptr, sc, nullptr,
                                           D, (long)L * 2 * D, (long)L * 2 * D,
                                           (long)L * L, L, 0);
    }

    // 3) softmax + split probs
    softmax512_split_kernel<<<Bn * L, 256>>>(sc, ps);

    // 4) out[b] = P[b] @ ioT[b]^T  (NT with pre-transposed io)
    {
        dim3 g(D / 128, L / 128, Bn);
        gemm_mma<0><<<g, 128, GEMM_SMEM>>>(ps, iosT, nullptr, out, nullptr,
                                           L, (long)L * 2 * L, (long)D * 2 * L,
                                           (long)L * D, D, 0);
    }
}